// round 4
// baseline (speedup 1.0000x reference)
#include <cuda_runtime.h>
#include <cuda_bf16.h>
#include <cstdint>

// out[b,i,:] = sum_j exp(q_i . k_j) * v_j   (B=4, S=4096, D=64, fp32)
// mma.sync bf16 split-precision (x = hi + lo; 3 MMAs per GEMM).
// R4: TQ=64, 2 CTAs/SM (occupancy overlap), V aliased over K buffer,
//     x4 ldmatrix for B operands.

#define S_LEN 4096
#define B_SZ  4
#define DD    64
#define TQ    64
#define TK    128
#define NTH   256
#define NTILES (S_LEN / TK)

#define QK_PITCH 144   // 64 bf16 + 8B pad
#define P_PITCH  272   // 128 bf16 + 8B pad

#define QBUF  (TQ * QK_PITCH)    //  9216
#define KVBUF (TK * QK_PITCH)    // 18432
#define PBUF  (TQ * P_PITCH)     // 17408

#define SM_Q  0
#define SM_KV (SM_Q + 2 * QBUF)      // 18432
#define SM_P  (SM_KV + 2 * KVBUF)    // 55296
#define SM_TOTAL (SM_P + 2 * PBUF)   // 90112 (88KB) -> 2 CTAs/SM

// ---------------- PTX helpers ----------------
__device__ __forceinline__ uint32_t smem_u32(const void* p) {
    uint32_t a;
    asm("{ .reg .u64 t; cvta.to.shared.u64 t, %1; cvt.u32.u64 %0, t; }" : "=r"(a) : "l"(p));
    return a;
}
#define LDMX4(r, a) \
    asm volatile("ldmatrix.sync.aligned.m8n8.x4.shared.b16 {%0,%1,%2,%3}, [%4];" \
        : "=r"((r)[0]), "=r"((r)[1]), "=r"((r)[2]), "=r"((r)[3]) : "r"(a))
#define LDMX4T(r, a) \
    asm volatile("ldmatrix.sync.aligned.m8n8.x4.trans.shared.b16 {%0,%1,%2,%3}, [%4];" \
        : "=r"((r)[0]), "=r"((r)[1]), "=r"((r)[2]), "=r"((r)[3]) : "r"(a))
#define MMA(c, av, bv) \
    asm volatile("mma.sync.aligned.m16n8k16.row.col.f32.bf16.bf16.f32 " \
        "{%0,%1,%2,%3}, {%4,%5,%6,%7}, {%8,%9}, {%0,%1,%2,%3};" \
        : "+f"((c)[0]), "+f"((c)[1]), "+f"((c)[2]), "+f"((c)[3]) \
        : "r"((av)[0]), "r"((av)[1]), "r"((av)[2]), "r"((av)[3]), \
          "r"((bv)[0]), "r"((bv)[1]))

__device__ __forceinline__ void split_pack(float x, float y, uint32_t& hi, uint32_t& lo) {
    __nv_bfloat16 xh = __float2bfloat16(x), yh = __float2bfloat16(y);
    float xr = x - __bfloat162float(xh);
    float yr = y - __bfloat162float(yh);
    __nv_bfloat16 xl = __float2bfloat16(xr), yl = __float2bfloat16(yr);
    hi = ((uint32_t)__bfloat16_as_ushort(yh) << 16) | (uint32_t)__bfloat16_as_ushort(xh);
    lo = ((uint32_t)__bfloat16_as_ushort(yl) << 16) | (uint32_t)__bfloat16_as_ushort(xl);
}

// stage a [rows x 64] fp32 tile into hi/lo bf16 buffers (pitch 144B), hi at sm, lo at sm+bufsz
template<int ROWS>
__device__ __forceinline__ void stage_tile(const float* __restrict__ g,
                                           char* smhi, int bufsz, int tid) {
    #pragma unroll
    for (int i = 0; i < (ROWS * 16) / NTH; ++i) {
        int f = tid + i * NTH;
        int row = f >> 4, d0 = (f & 15) << 2;
        float4 t = *(const float4*)&g[(size_t)row * DD + d0];
        uint32_t h0, l0, h1, l1;
        split_pack(t.x, t.y, h0, l0);
        split_pack(t.z, t.w, h1, l1);
        int off = row * QK_PITCH + d0 * 2;
        *(uint2*)(smhi + off)         = make_uint2(h0, h1);
        *(uint2*)(smhi + bufsz + off) = make_uint2(l0, l1);
    }
}

__global__ void __launch_bounds__(NTH, 2)
fa_mma2_kernel(const float* __restrict__ q, const float* __restrict__ k,
               const float* __restrict__ v, float* __restrict__ out)
{
    extern __shared__ char smem[];
    const uint32_t sb = smem_u32(smem);
    const int tid  = threadIdx.x;
    const int wid  = tid >> 5;
    const int lane = tid & 31;
    const int b  = blockIdx.y;
    const int q0 = blockIdx.x * TQ;

    const int wrow  = (wid & 3) * 16;   // S/O row base (0..48)
    const int wcolS = (wid >> 2) * 64;  // S col base
    const int wcolO = (wid >> 2) * 32;  // O col base

    const float* Qg = q + ((size_t)b * S_LEN + q0) * DD;
    const float* Kg = k + (size_t)b * S_LEN * DD;
    const float* Vg = v + (size_t)b * S_LEN * DD;
    float*       Og = out + ((size_t)b * S_LEN + q0) * DD;

    // ---- stage Q once ----
    stage_tile<TQ>(Qg, smem + SM_Q, QBUF, tid);

    // per-lane ldmatrix addresses
    const uint32_t aQ = sb + SM_Q +
        (uint32_t)((wrow + (lane & 15)) * QK_PITCH + (lane >> 4) * 16);
    // K (B of GEMM1), x4: n-pair p covers cols wcolS+p*16 .. +15
    const uint32_t bK = sb + SM_KV +
        (uint32_t)((wcolS + ((lane >> 4) & 1) * 8 + (lane & 7)) * QK_PITCH +
                   ((lane >> 3) & 1) * 16);
    // P (A of GEMM2)
    const uint32_t aP = sb + SM_P +
        (uint32_t)((wrow + (lane & 15)) * P_PITCH + (lane >> 4) * 16);
    // V (B of GEMM2, trans), x4: d-pair p covers cols wcolO+p*16 .. +15
    const uint32_t bV = sb + SM_KV +
        (uint32_t)((((lane >> 3) & 1) * 8 + (lane & 7)) * QK_PITCH +
                   (wcolO + ((lane >> 4) & 1) * 8) * 2);
    // P writes
    const uint32_t pW = sb + SM_P +
        (uint32_t)((wrow + (lane >> 2)) * P_PITCH + (wcolS + (lane & 3) * 2) * 2);

    float acc2[4][4];
    #pragma unroll
    for (int ni = 0; ni < 4; ++ni)
        #pragma unroll
        for (int e = 0; e < 4; ++e) acc2[ni][e] = 0.0f;

    for (int t = 0; t < NTILES; ++t) {
        __syncthreads();   // A: prev GEMM2 done reading KV(V)+P; Q ready (t=0)

        stage_tile<TK>(Kg + (size_t)(t * TK) * DD, smem + SM_KV, KVBUF, tid);
        __syncthreads();   // B: K visible

        // ---- GEMM1: S(64x128) = Q @ K^T, 3-term ----
        float acc1[8][4];
        #pragma unroll
        for (int ni = 0; ni < 8; ++ni)
            #pragma unroll
            for (int e = 0; e < 4; ++e) acc1[ni][e] = 0.0f;

        #pragma unroll
        for (int ks = 0; ks < 4; ++ks) {
            uint32_t ahi[4], alo[4];
            uint32_t a = aQ + (uint32_t)(ks * 32);
            LDMX4(ahi, a);
            LDMX4(alo, a + QBUF);
            #pragma unroll
            for (int p = 0; p < 4; ++p) {       // n-pairs: ni = 2p, 2p+1
                uint32_t bb = bK + (uint32_t)(p * 16 * QK_PITCH + ks * 32);
                uint32_t bhi[4], blo[4];
                LDMX4(bhi, bb);
                LDMX4(blo, bb + KVBUF);
                MMA(acc1[2*p],   ahi, bhi);
                MMA(acc1[2*p],   ahi, blo);
                MMA(acc1[2*p],   alo, bhi);
                MMA(acc1[2*p+1], ahi, bhi + 2);
                MMA(acc1[2*p+1], ahi, blo + 2);
                MMA(acc1[2*p+1], alo, bhi + 2);
            }
        }
        __syncthreads();   // C: all warps done reading K -> KV free for V

        // ---- stage V over KV; exp+split P ----
        stage_tile<TK>(Vg + (size_t)(t * TK) * DD, smem + SM_KV, KVBUF, tid);

        #pragma unroll
        for (int ni = 0; ni < 8; ++ni) {
            float e0 = __expf(acc1[ni][0]);
            float e1 = __expf(acc1[ni][1]);
            float e2 = __expf(acc1[ni][2]);
            float e3 = __expf(acc1[ni][3]);
            uint32_t h01, l01, h23, l23;
            split_pack(e0, e1, h01, l01);
            split_pack(e2, e3, h23, l23);
            uint32_t w0 = pW + (uint32_t)(ni * 16);
            uint32_t w1 = w0 + 8 * P_PITCH;
            asm volatile("st.shared.b32 [%0], %1;" :: "r"(w0), "r"(h01));
            asm volatile("st.shared.b32 [%0], %1;" :: "r"(w0 + PBUF), "r"(l01));
            asm volatile("st.shared.b32 [%0], %1;" :: "r"(w1), "r"(h23));
            asm volatile("st.shared.b32 [%0], %1;" :: "r"(w1 + PBUF), "r"(l23));
        }
        __syncthreads();   // D: V + P visible

        // ---- GEMM2: O(64x64) += P @ V, 3-term ----
        #pragma unroll
        for (int ks = 0; ks < 8; ++ks) {
            uint32_t ahi[4], alo[4];
            uint32_t a = aP + (uint32_t)(ks * 32);
            LDMX4(ahi, a);
            LDMX4(alo, a + PBUF);
            #pragma unroll
            for (int p = 0; p < 2; ++p) {       // d-pairs: ni = 2p, 2p+1
                uint32_t bb = bV + (uint32_t)(ks * 16 * QK_PITCH + p * 32);
                uint32_t bhi[4], blo[4];
                LDMX4T(bhi, bb);
                LDMX4T(blo, bb + KVBUF);
                MMA(acc2[2*p],   ahi, bhi);
                MMA(acc2[2*p],   ahi, blo);
                MMA(acc2[2*p],   alo, bhi);
                MMA(acc2[2*p+1], ahi, bhi + 2);
                MMA(acc2[2*p+1], ahi, blo + 2);
                MMA(acc2[2*p+1], alo, bhi + 2);
            }
        }
    }

    // ---- epilogue ----
    #pragma unroll
    for (int ni = 0; ni < 4; ++ni) {
        int r = wrow + (lane >> 2);
        int c = wcolO + ni * 8 + (lane & 3) * 2;
        *(float2*)&Og[(size_t)r * DD + c] = make_float2(acc2[ni][0], acc2[ni][1]);
        *(float2*)&Og[(size_t)(r + 8) * DD + c] = make_float2(acc2[ni][2], acc2[ni][3]);
    }
}

extern "C" void kernel_launch(void* const* d_in, const int* in_sizes, int n_in,
                              void* d_out, int out_size)
{
    const float* q = (const float*)d_in[0];
    const float* k = (const float*)d_in[1];
    const float* v = (const float*)d_in[2];
    float* out = (float*)d_out;
    (void)in_sizes; (void)n_in; (void)out_size;

    cudaFuncSetAttribute(fa_mma2_kernel,
                         cudaFuncAttributeMaxDynamicSharedMemorySize, SM_TOTAL);
    dim3 grid(S_LEN / TQ, B_SZ);   // 64 x 4 = 256 CTAs, 2/SM, one wave
    fa_mma2_kernel<<<grid, NTH, SM_TOTAL>>>(q, k, v, out);
}

// round 5
// speedup vs baseline: 1.2972x; 1.2972x over previous
#include <cuda_runtime.h>
#include <cuda_bf16.h>
#include <cstdint>

// out[b,i,:] = sum_j exp(q_i . k_j) * v_j   (B=4, S=4096, D=64, fp32)
// mma.sync bf16 split-precision, FA-style register reuse:
//  - warp owns 16 full rows of S -> S C-frags == P A-frags (no P smem trip)
//  - Q A-frags persistent in registers (x log2e folded in)
//  - K/V staging software-pipelined (LDG t+1 hidden under MMAs of t)

#define S_LEN 4096
#define B_SZ  4
#define DD    64
#define TQ    128
#define TK    128
#define NTH   256
#define NTILES (S_LEN / TK)

#define PITCH 144              // 64 bf16 + 8B pad
#define KBUF  (TK * PITCH)     // 18432 per hi/lo buffer

#define SM_K  0                       // K hi @0, K lo @KBUF
#define SM_V  (2 * KBUF)              // V hi, V lo
#define SM_TOTAL (4 * KBUF)           // 73728 B

#define LOG2E 1.4426950408889634f

// ---------------- PTX helpers ----------------
__device__ __forceinline__ uint32_t smem_u32(const void* p) {
    uint32_t a;
    asm("{ .reg .u64 t; cvta.to.shared.u64 t, %1; cvt.u32.u64 %0, t; }" : "=r"(a) : "l"(p));
    return a;
}
#define LDMX4(r, a) \
    asm volatile("ldmatrix.sync.aligned.m8n8.x4.shared.b16 {%0,%1,%2,%3}, [%4];" \
        : "=r"((r)[0]), "=r"((r)[1]), "=r"((r)[2]), "=r"((r)[3]) : "r"(a))
#define LDMX4T(r, a) \
    asm volatile("ldmatrix.sync.aligned.m8n8.x4.trans.shared.b16 {%0,%1,%2,%3}, [%4];" \
        : "=r"((r)[0]), "=r"((r)[1]), "=r"((r)[2]), "=r"((r)[3]) : "r"(a))
#define MMA(c, av, bv) \
    asm volatile("mma.sync.aligned.m16n8k16.row.col.f32.bf16.bf16.f32 " \
        "{%0,%1,%2,%3}, {%4,%5,%6,%7}, {%8,%9}, {%0,%1,%2,%3};" \
        : "+f"((c)[0]), "+f"((c)[1]), "+f"((c)[2]), "+f"((c)[3]) \
        : "r"((av)[0]), "r"((av)[1]), "r"((av)[2]), "r"((av)[3]), \
          "r"((bv)[0]), "r"((bv)[1]))

__device__ __forceinline__ float ex2f(float x) {
    float r;
    asm("ex2.approx.ftz.f32 %0, %1;" : "=f"(r) : "f"(x));
    return r;
}
__device__ __forceinline__ void split_pack(float x, float y, uint32_t& hi, uint32_t& lo) {
    __nv_bfloat16 xh = __float2bfloat16(x), yh = __float2bfloat16(y);
    float xr = x - __bfloat162float(xh);
    float yr = y - __bfloat162float(yh);
    __nv_bfloat16 xl = __float2bfloat16(xr), yl = __float2bfloat16(yr);
    hi = ((uint32_t)__bfloat16_as_ushort(yh) << 16) | (uint32_t)__bfloat16_as_ushort(xh);
    lo = ((uint32_t)__bfloat16_as_ushort(yl) << 16) | (uint32_t)__bfloat16_as_ushort(xl);
}

// LDG a [128 x 64] fp32 tile into 8 float4 regs per thread
__device__ __forceinline__ void ldg_tile(const float* __restrict__ g, float4 r[8], int tid) {
    #pragma unroll
    for (int i = 0; i < 8; ++i) {
        int f = tid + i * NTH;
        int row = f >> 4, d0 = (f & 15) << 2;
        r[i] = *(const float4*)&g[(size_t)row * DD + d0];
    }
}
// split+store those regs to hi/lo bf16 smem (pitch 144), optional scale
__device__ __forceinline__ void sts_tile(const float4 r[8], char* smhi, int tid, float scale) {
    #pragma unroll
    for (int i = 0; i < 8; ++i) {
        int f = tid + i * NTH;
        int row = f >> 4, d0 = (f & 15) << 2;
        uint32_t h0, l0, h1, l1;
        split_pack(r[i].x * scale, r[i].y * scale, h0, l0);
        split_pack(r[i].z * scale, r[i].w * scale, h1, l1);
        int off = row * PITCH + d0 * 2;
        *(uint2*)(smhi + off)        = make_uint2(h0, h1);
        *(uint2*)(smhi + KBUF + off) = make_uint2(l0, l1);
    }
}

__global__ void __launch_bounds__(NTH, 1)
fa_fa_kernel(const float* __restrict__ q, const float* __restrict__ k,
             const float* __restrict__ v, float* __restrict__ out)
{
    extern __shared__ char smem[];
    const uint32_t sb = smem_u32(smem);
    const int tid  = threadIdx.x;
    const int wid  = tid >> 5;
    const int lane = tid & 31;
    const int b  = blockIdx.y;
    const int q0 = blockIdx.x * TQ;

    const float* Qg = q + ((size_t)b * S_LEN + q0) * DD;
    const float* Kg = k + (size_t)b * S_LEN * DD;
    const float* Vg = v + (size_t)b * S_LEN * DD;
    float*       Og = out + ((size_t)b * S_LEN + q0) * DD;

    // ---- prologue: stage Q (scaled by log2e) through K buffer, grab A-frags ----
    float4 pf[8];
    ldg_tile(Qg, pf, tid);
    sts_tile(pf, smem + SM_K, tid, LOG2E);
    __syncthreads();

    uint32_t qhi[4][4], qlo[4][4];
    {
        const uint32_t aQ = sb + SM_K +
            (uint32_t)((wid * 16 + (lane & 15)) * PITCH + (lane >> 4) * 16);
        #pragma unroll
        for (int ks = 0; ks < 4; ++ks) {
            LDMX4(qhi[ks], aQ + ks * 32);
            LDMX4(qlo[ks], aQ + KBUF + ks * 32);
        }
    }
    __syncthreads();

    // stage K0, V0
    ldg_tile(Kg, pf, tid);
    sts_tile(pf, smem + SM_K, tid, 1.0f);
    ldg_tile(Vg, pf, tid);
    sts_tile(pf, smem + SM_V, tid, 1.0f);
    __syncthreads();

    // per-lane B-operand ldmatrix bases
    const uint32_t bK = sb + SM_K +
        (uint32_t)(( ((lane >> 4) & 1) * 8 + (lane & 7) ) * PITCH + ((lane >> 3) & 1) * 16);
    const uint32_t bV = sb + SM_V +
        (uint32_t)(( ((lane >> 3) & 1) * 8 + (lane & 7) ) * PITCH + (((lane >> 4) & 1) * 8) * 2);

    float acc2[8][4];
    #pragma unroll
    for (int ni = 0; ni < 8; ++ni)
        #pragma unroll
        for (int e = 0; e < 4; ++e) acc2[ni][e] = 0.0f;

    for (int t = 0; t < NTILES; ++t) {
        const int tn = (t + 1 < NTILES) ? t + 1 : 0;   // clamped prefetch

        // ---- prefetch K(t+1); GEMM1(t): S(16 x 128 per warp) ----
        ldg_tile(Kg + (size_t)(tn * TK) * DD, pf, tid);

        float acc1[16][4];
        #pragma unroll
        for (int n = 0; n < 16; ++n)
            #pragma unroll
            for (int e = 0; e < 4; ++e) acc1[n][e] = 0.0f;

        #pragma unroll
        for (int ks = 0; ks < 4; ++ks) {
            #pragma unroll
            for (int p = 0; p < 8; ++p) {     // n-pairs: blocks 2p, 2p+1
                uint32_t bb = bK + (uint32_t)(p * 16 * PITCH + ks * 32);
                uint32_t bhi[4], blo[4];
                LDMX4(bhi, bb);
                LDMX4(blo, bb + KBUF);
                MMA(acc1[2*p],   qhi[ks], bhi);
                MMA(acc1[2*p],   qhi[ks], blo);
                MMA(acc1[2*p],   qlo[ks], bhi);
                MMA(acc1[2*p+1], qhi[ks], bhi + 2);
                MMA(acc1[2*p+1], qhi[ks], blo + 2);
                MMA(acc1[2*p+1], qlo[ks], bhi + 2);
            }
        }

        // ---- P = 2^S in registers, split to hi/lo A-frags ----
        uint32_t phi[8][4], plo[8][4];
        #pragma unroll
        for (int j = 0; j < 8; ++j) {
            #pragma unroll
            for (int r = 0; r < 2; ++r) {     // n-block 2j+r -> A regs 2r..2r+1
                int n = 2 * j + r;
                float e0 = ex2f(acc1[n][0]);
                float e1 = ex2f(acc1[n][1]);
                float e2 = ex2f(acc1[n][2]);
                float e3 = ex2f(acc1[n][3]);
                split_pack(e0, e1, phi[j][2*r],     plo[j][2*r]);
                split_pack(e2, e3, phi[j][2*r + 1], plo[j][2*r + 1]);
            }
        }
        __syncthreads();                      // all warps done reading K(t)

        // K(t+1) becomes visible at the next barrier; V(t+1) prefetch under GEMM2
        sts_tile(pf, smem + SM_K, tid, 1.0f);
        ldg_tile(Vg + (size_t)(tn * TK) * DD, pf, tid);

        // ---- GEMM2(t): O(16 x 64 per warp) += P @ V ----
        #pragma unroll
        for (int ks = 0; ks < 8; ++ks) {
            #pragma unroll
            for (int p = 0; p < 4; ++p) {     // d-pairs: blocks 2p, 2p+1
                uint32_t bb = bV + (uint32_t)(ks * 16 * PITCH + p * 32);
                uint32_t bhi[4], blo[4];
                LDMX4T(bhi, bb);
                LDMX4T(blo, bb + KBUF);
                MMA(acc2[2*p],   phi[ks], bhi);
                MMA(acc2[2*p],   phi[ks], blo);
                MMA(acc2[2*p],   plo[ks], bhi);
                MMA(acc2[2*p+1], phi[ks], bhi + 2);
                MMA(acc2[2*p+1], phi[ks], blo + 2);
                MMA(acc2[2*p+1], plo[ks], bhi + 2);
            }
        }
        __syncthreads();                      // all warps done reading V(t); K(t+1) visible
        sts_tile(pf, smem + SM_V, tid, 1.0f); // V(t+1); visible at next barrier
    }

    // ---- epilogue: O rows wid*16 .. +16 ----
    #pragma unroll
    for (int ni = 0; ni < 8; ++ni) {
        int r = wid * 16 + (lane >> 2);
        int c = ni * 8 + (lane & 3) * 2;
        *(float2*)&Og[(size_t)r * DD + c]       = make_float2(acc2[ni][0], acc2[ni][1]);
        *(float2*)&Og[(size_t)(r + 8) * DD + c] = make_float2(acc2[ni][2], acc2[ni][3]);
    }
}

extern "C" void kernel_launch(void* const* d_in, const int* in_sizes, int n_in,
                              void* d_out, int out_size)
{
    const float* q = (const float*)d_in[0];
    const float* k = (const float*)d_in[1];
    const float* v = (const float*)d_in[2];
    float* out = (float*)d_out;
    (void)in_sizes; (void)n_in; (void)out_size;

    cudaFuncSetAttribute(fa_fa_kernel,
                         cudaFuncAttributeMaxDynamicSharedMemorySize, SM_TOTAL);
    dim3 grid(S_LEN / TQ, B_SZ);   // 32 x 4 = 128 CTAs, one wave
    fa_fa_kernel<<<grid, NTH, SM_TOTAL>>>(q, k, v, out);
}